// round 15
// baseline (speedup 1.0000x reference)
#include <cuda_runtime.h>
#include <cuda_fp16.h>
#include <cstdint>
#include <math.h>

// ---------------------------------------------------------------------------
// SambaMixerBlock: B=8, S=D=1024, N=16, DCONV=4, EXPAND=2 -> DI=2048, DT_RANK=64
// Round 15: scan prefetch queue 8 -> 16 (covers ~960cyc > DRAM latency).
//           Everything else frozen at the round-14 best config.
// ---------------------------------------------------------------------------

#define BSZ   8
#define SEQ   1024
#define DM    1024
#define DI_   2048
#define NST   16
#define DTR   64
#define XD    96
#define ROWS  (BSZ*SEQ)
#define KSP   4                      // x_proj split-K factor
#define QD    16                     // scan prefetch queue depth

// fp32 scratch
__device__ float g_xdbl[(size_t)ROWS * XD];
__device__ float g_xpart[(size_t)KSP * ROWS * XD];
__device__ float g_res1[(size_t)ROWS * DM];
__device__ float g_outm[(size_t)ROWS * DM];
// fp16 scratch
__device__ __half g_xzh [(size_t)ROWS * 2 * DI_];
__device__ __half g_xh16[(size_t)ROWS * DI_];
__device__ __half g_y16 [(size_t)ROWS * DI_];
__device__ __half g_dtb16[(size_t)ROWS * DI_];
__device__ __half g_dth [(size_t)ROWS * DTR];
__device__ __half g_mix16[(size_t)ROWS * DM];
__device__ __half g_tmp16[(size_t)ROWS * DM];

// converted weights: per path IN | XPROJ | DT | OUT
#define W_IN   0
#define W_XP   (2 * DI_ * DM)
#define W_DT   (W_XP + XD * DI_)
#define W_OUT  (W_DT + DI_ * DTR)
#define W_STRIDE (W_OUT + DM * DI_)
__device__ __half g_wh[(size_t)2 * W_STRIDE];

// ---------------------------------------------------------------------------
__device__ __forceinline__ void cpa16(uint32_t d, const void* s)
{
    asm volatile("cp.async.cg.shared.global [%0], [%1], 16;" :: "r"(d), "l"(s));
}
__device__ __forceinline__ void cpa16z(uint32_t d, const void* s, bool ok)
{
    int sz = ok ? 16 : 0;
    asm volatile("cp.async.cg.shared.global [%0], [%1], 16, %2;"
                 :: "r"(d), "l"(s), "r"(sz));
}
#define CP_COMMIT() asm volatile("cp.async.commit_group;" ::: "memory")
#define CP_WAIT1()  asm volatile("cp.async.wait_group 1;" ::: "memory")

__device__ __forceinline__ void mma16816(float* d, const uint32_t* a, const uint32_t* b)
{
    asm volatile(
        "mma.sync.aligned.m16n8k16.row.col.f32.f16.f16.f32 "
        "{%0,%1,%2,%3}, {%4,%5,%6,%7}, {%8,%9}, {%0,%1,%2,%3};"
        : "+f"(d[0]), "+f"(d[1]), "+f"(d[2]), "+f"(d[3])
        : "r"(a[0]), "r"(a[1]), "r"(a[2]), "r"(a[3]), "r"(b[0]), "r"(b[1]));
}

__device__ __forceinline__ void ldmx4(uint32_t* r, uint32_t addr)
{
    asm volatile("ldmatrix.sync.aligned.m8n8.x4.shared.b16 {%0,%1,%2,%3}, [%4];"
                 : "=r"(r[0]), "=r"(r[1]), "=r"(r[2]), "=r"(r[3]) : "r"(addr));
}

// ---------------------------------------------------------------------------
// Pipelined HMMA GEMM: CTA 128x128, 8 warps (64x32), BK=32, 3-stage cp.async,
// ldmatrix, 80B row stride, 2 CTAs/SM. EPI: softplus(C+bias). OUTH: fp16 C.
// ---------------------------------------------------------------------------
template<int EPI, int OUTH>
__global__ __launch_bounds__(256, 2) void gemm_cp(
    const __half* __restrict__ A, int lda,
    const __half* __restrict__ Bm,
    const float* __restrict__ bias, void* __restrict__ Cbase,
    int M, int Nsz, int Kfull, int Ksub)
{
    constexpr int TN  = 128;
    constexpr int ABY = 128 * 80;
    constexpr int BBY = TN * 80;
    constexpr int STG = ABY + BBY;
    constexpr int JN  = TN / 32;

    extern __shared__ __align__(16) char smem[];
    const uint32_t sb0 = (uint32_t)__cvta_generic_to_shared(smem);

    const int tid = threadIdx.x, wid = tid >> 5, lid = tid & 31;
    const int bm = blockIdx.y * 128, bn = blockIdx.x * TN;
    const int koff = blockIdx.z * Ksub;
    const int wm = (wid & 1) * 64, wn = (wid >> 1) * 32;
    const int g = lid >> 2, t4 = lid & 3;
    const int S = Ksub >> 5;

    const int lr = lid & 7, tq = lid >> 3;
    const int a_ro = (tq & 1) * 8, a_co = (tq >> 1) * 16;
    const int b_ro = (tq >> 1) * 8, b_co = (tq & 1) * 16;

    auto issue = [&](int s) {
        const int k0 = koff + (s << 5);
        const uint32_t st = sb0 + (s % 3) * STG;
#pragma unroll
        for (int i = 0; i < 2; i++) {
            const int id = tid + i * 256, row = id >> 2, q = id & 3;
            const size_t go = (size_t)(bm + row) * lda + k0 + q * 8;
            cpa16(st + row * 80 + q * 16, A + go);
        }
#pragma unroll
        for (int i = 0; i < 2; i++) {
            const int id = tid + i * 256, row = id >> 2, q = id & 3;
            const bool ok = (bn + row) < Nsz;
            const int r2 = ok ? (bn + row) : 0;
            const size_t go = (size_t)r2 * Kfull + k0 + q * 8;
            cpa16z(st + ABY + row * 80 + q * 16, Bm + go, ok);
        }
    };

    float acc[4][JN][4];
#pragma unroll
    for (int i = 0; i < 4; i++)
#pragma unroll
        for (int j = 0; j < JN; j++)
#pragma unroll
            for (int c = 0; c < 4; c++) acc[i][j][c] = 0.f;

    issue(0); CP_COMMIT();
    if (S > 1) issue(1);
    CP_COMMIT();

    for (int s = 0; s < S; s++) {
        CP_WAIT1();
        __syncthreads();
        if (s + 2 < S) issue(s + 2);
        CP_COMMIT();

        const uint32_t st = sb0 + (s % 3) * STG;
#pragma unroll
        for (int kk = 0; kk < 2; kk++) {
            const int cb = kk * 32;
            uint32_t ah[4][4];
#pragma unroll
            for (int i = 0; i < 4; i++)
                ldmx4(ah[i], st + (wm + i * 16 + a_ro + lr) * 80 + cb + a_co);
#pragma unroll
            for (int j2 = 0; j2 < JN / 2; j2++) {
                uint32_t bh[4];
                ldmx4(bh, st + ABY + (wn + j2 * 16 + b_ro + lr) * 80 + cb + b_co);
#pragma unroll
                for (int i = 0; i < 4; i++) {
                    mma16816(acc[i][2 * j2],     ah[i], bh);
                    mma16816(acc[i][2 * j2 + 1], ah[i], bh + 2);
                }
            }
        }
    }

#pragma unroll
    for (int i = 0; i < 4; i++) {
        const int r0 = bm + wm + i * 16 + g;
#pragma unroll
        for (int j = 0; j < JN; j++) {
            const int c = bn + wn + j * 8 + t4 * 2;
            if (c < Nsz) {
                float v0 = acc[i][j][0], v1 = acc[i][j][1];
                float v2 = acc[i][j][2], v3 = acc[i][j][3];
                if (EPI == 1) {
                    const float b0 = bias[c], b1 = bias[c + 1];
                    v0 += b0; v1 += b1; v2 += b0; v3 += b1;
                    v0 = (v0 > 20.f) ? v0 : __logf(1.f + __expf(v0));
                    v1 = (v1 > 20.f) ? v1 : __logf(1.f + __expf(v1));
                    v2 = (v2 > 20.f) ? v2 : __logf(1.f + __expf(v2));
                    v3 = (v3 > 20.f) ? v3 : __logf(1.f + __expf(v3));
                }
                if (OUTH) {
                    __half* C = (__half*)Cbase + (size_t)blockIdx.z * M * Nsz;
                    *(__half2*)(C + (size_t)r0 * Nsz + c) = __floats2half2_rn(v0, v1);
                    *(__half2*)(C + (size_t)(r0 + 8) * Nsz + c) = __floats2half2_rn(v2, v3);
                } else {
                    float* C = (float*)Cbase + (size_t)blockIdx.z * M * Nsz;
                    *(float2*)(C + (size_t)r0 * Nsz + c)       = make_float2(v0, v1);
                    *(float2*)(C + (size_t)(r0 + 8) * Nsz + c) = make_float2(v2, v3);
                }
            }
        }
    }
}

// ---------------------------------------------------------------------------
struct WSeg { const float* src; __half* dst; int n; };
struct W8   { WSeg s[8]; };

__global__ __launch_bounds__(256) void convert_all_kernel(W8 segs)
{
    const int stride = gridDim.x * 256;
    const int t0 = blockIdx.x * 256 + threadIdx.x;
#pragma unroll
    for (int k = 0; k < 8; k++) {
        const float* src = segs.s[k].src;
        __half* dst = segs.s[k].dst;
        const int n = segs.s[k].n;
        for (int i = t0; i < n; i += stride)
            dst[i] = __float2half_rn(src[i]);
    }
}

// reduce split-K partials -> compact fp32 xdbl + fp16 dt-rank slice
__global__ __launch_bounds__(256) void reduce_xproj_kernel(
    const float* __restrict__ part, float* __restrict__ xdbl,
    __half* __restrict__ dth)
{
    const size_t n1 = (size_t)ROWS * XD;
    const size_t i = (size_t)blockIdx.x * 256 + threadIdx.x;
    float s = part[i] + part[i + n1] + part[i + 2 * n1] + part[i + 3 * n1];
    xdbl[i] = s;
    const int col = (int)(i % XD);
    if (col < DTR) dth[(i / XD) * DTR + col] = __float2half_rn(s);
}

// ---------------------------------------------------------------------------
// Depthwise causal conv + bias + SiLU; 2 channels x 4 l-steps per thread.
// ---------------------------------------------------------------------------
__global__ __launch_bounds__(256) void conv_silu_kernel(
    const __half* __restrict__ xz, const float* __restrict__ w,
    const float* __restrict__ bias, __half* __restrict__ xh)
{
    const long i = (long)blockIdx.x * 256 + threadIdx.x;   // over (ROWS/4)*(DI/2)
    const int  d2 = (int)(i & (DI_ / 2 - 1));
    const int  d  = d2 * 2;
    const long bl4 = i >> 10;
    const int  l0 = (int)(bl4 & (SEQ / 4 - 1)) * 4;
    const long b  = bl4 >> 8;

    const __half* base = xz + ((size_t)b * SEQ) * (2 * DI_) + d;
    const float2 bs = *(const float2*)(bias + d);
    const float4 wa = *(const float4*)(w + d * 4);
    const float4 wb = *(const float4*)(w + d * 4 + 4);

    float2 f[7];
#pragma unroll
    for (int j = 0; j < 7; j++) {
        const int l = l0 - 3 + j;
        if (l >= 0)
            f[j] = __half22float2(*(const __half2*)(base + (size_t)l * (2 * DI_)));
        else
            f[j] = make_float2(0.f, 0.f);
    }

    __half* op = xh + ((size_t)b * SEQ + l0) * DI_ + d;
#pragma unroll
    for (int k = 0; k < 4; k++) {
        float a0 = bs.x + wa.x * f[k].x + wa.y * f[k + 1].x
                        + wa.z * f[k + 2].x + wa.w * f[k + 3].x;
        float a1 = bs.y + wb.x * f[k].y + wb.y * f[k + 1].y
                        + wb.z * f[k + 2].y + wb.w * f[k + 3].y;
        a0 = a0 / (1.f + __expf(-a0));
        a1 = a1 / (1.f + __expf(-a1));
        *(__half2*)(op + (size_t)k * DI_) = __floats2half2_rn(a0, a1);
    }
}

// ---------------------------------------------------------------------------
// Selective scan: 1 warp/block, 16-deep register queues (explicit unroll),
// single coalesced B/C load from compact xdbl, 4-chain acc.
// ---------------------------------------------------------------------------
__global__ __launch_bounds__(32) void scan_kernel(
    const __half* __restrict__ dtb, const __half* __restrict__ xh,
    const float* __restrict__ xdbl, const __half* __restrict__ xz,
    const float* __restrict__ A_log, const float* __restrict__ Dp,
    __half* __restrict__ y)
{
    const int b = blockIdx.y;
    const int lane = threadIdx.x;
    const int d = blockIdx.x * 32 + lane;

    float A[NST], h[NST];
#pragma unroll
    for (int n = 0; n < NST; n++) {
        A[n] = -__expf(A_log[d * NST + n]);
        h[n] = 0.f;
    }
    const float A0 = A[0];
    bool uni = true;
#pragma unroll
    for (int n = 1; n < NST; n++)
        uni = uni && (fabsf(A[n] - (n + 1) * A0) <= 1e-3f * (n + 1) * fabsf(A0) + 1e-12f);
    const float dval = Dp[d];

    const size_t rowbase = (size_t)b * SEQ;

    __half dq[QD], xq[QD], zq[QD];
    float bcq[QD];
#pragma unroll
    for (int p = 0; p < QD; p++) {
        const size_t idx = (rowbase + p) * DI_ + d;
        dq[p]  = dtb[idx];
        xq[p]  = xh[idx];
        zq[p]  = xz[(rowbase + p) * (2 * DI_) + DI_ + d];
        bcq[p] = xdbl[(rowbase + p) * XD + DTR + lane];
    }

    for (int l0 = 0; l0 < SEQ; l0 += QD) {
#pragma unroll
        for (int p = 0; p < QD; p++) {
            const int l = l0 + p;
            const float dtv = __half2float(dq[p]);
            const float xv  = __half2float(xq[p]);
            const float zv  = __half2float(zq[p]);
            const float bcv = bcq[p];

            const int lp = (l + QD < SEQ) ? l + QD : SEQ - 1;
            const size_t idx2 = (rowbase + lp) * DI_ + d;
            dq[p]  = dtb[idx2];
            xq[p]  = xh[idx2];
            zq[p]  = xz[(rowbase + lp) * (2 * DI_) + DI_ + d];
            bcq[p] = xdbl[(rowbase + lp) * XD + DTR + lane];

            const float dx = dtv * xv;
            float acc4[4] = {0.f, 0.f, 0.f, 0.f};
            if (uni) {
                const float p1 = __expf(dtv * A0);
                float e[NST];
                e[0] = p1;
                e[1] = p1 * p1;
                e[2] = e[1] * p1;
                e[3] = e[1] * e[1];
#pragma unroll
                for (int n = 4; n < NST; n++) e[n] = e[n - 4] * e[3];
#pragma unroll
                for (int n = 0; n < NST; n++) {
                    const float Bn = __shfl_sync(0xffffffffu, bcv, n);
                    const float Cn = __shfl_sync(0xffffffffu, bcv, 16 + n);
                    h[n] = e[n] * h[n] + dx * Bn;
                    acc4[n & 3] += h[n] * Cn;
                }
            } else {
#pragma unroll
                for (int n = 0; n < NST; n++) {
                    const float Bn = __shfl_sync(0xffffffffu, bcv, n);
                    const float Cn = __shfl_sync(0xffffffffu, bcv, 16 + n);
                    h[n] = __expf(dtv * A[n]) * h[n] + dx * Bn;
                    acc4[n & 3] += h[n] * Cn;
                }
            }
            float acc = (acc4[0] + acc4[1]) + (acc4[2] + acc4[3]);
            acc += xv * dval;
            acc *= zv / (1.f + __expf(-zv));
            y[(rowbase + l) * DI_ + d] = __float2half_rn(acc);
        }
    }
}

// ---------------------------------------------------------------------------
__device__ __forceinline__ float block_sum256(float v)
{
    __shared__ float red[8];
    const int lane = threadIdx.x & 31, w = threadIdx.x >> 5;
#pragma unroll
    for (int o = 16; o; o >>= 1) v += __shfl_xor_sync(0xffffffffu, v, o);
    if (!lane) red[w] = v;
    __syncthreads();
    if (w == 0) {
        v = (lane < 8) ? red[lane] : 0.f;
#pragma unroll
        for (int o = 4; o; o >>= 1) v += __shfl_xor_sync(0xffffffffu, v, o);
        if (!lane) red[0] = v;
    }
    __syncthreads();
    return red[0];
}

__global__ __launch_bounds__(256) void rms_mix_tm_kernel(
    const float* __restrict__ residual, const float* __restrict__ hstm,
    const float* __restrict__ hscm, const float* __restrict__ nw,
    const float* __restrict__ wavg, float* __restrict__ res1,
    __half* __restrict__ omix)
{
    const int bs = blockIdx.x, b = bs >> 10, s = bs & 1023, t = threadIdx.x;
    const size_t r4 = (size_t)bs * 256 + t;
    const size_t i0 = ((size_t)(b * 2 + 0) * 1024 + s) * 256 + t;
    const size_t i1 = ((size_t)(b * 2 + 1) * 1024 + s) * 256 + t;

    float4 r  = ((const float4*)residual)[r4];
    float4 c1 = ((const float4*)hscm)[i1];
    r.x += c1.x; r.y += c1.y; r.z += c1.z; r.w += c1.w;
    ((float4*)res1)[r4] = r;

    const float tot = block_sum256(r.x * r.x + r.y * r.y + r.z * r.z + r.w * r.w);
    const float scale = rsqrtf(tot * (1.f / (float)DM) + 1e-5f);

    float w0 = wavg[s], w1 = wavg[1024 + s], w2 = wavg[2048 + s], w3 = wavg[3072 + s];
    const float mx = fmaxf(fmaxf(w0, w1), fmaxf(w2, w3));
    w0 = __expf(w0 - mx); w1 = __expf(w1 - mx); w2 = __expf(w2 - mx); w3 = __expf(w3 - mx);
    const float inv = 1.f / (w0 + w1 + w2 + w3);
    w0 *= inv; w1 *= inv; w2 *= inv; w3 *= inv;

    const float4 a0 = ((const float4*)hstm)[i0];
    const float4 a1 = ((const float4*)hstm)[i1];
    const float4 c0 = ((const float4*)hscm)[i0];
    const float4 wn = ((const float4*)nw)[t];
    float o0 = w0 * a0.x + w1 * a1.x + w2 * c0.x + w3 * (r.x * scale * wn.x);
    float o1 = w0 * a0.y + w1 * a1.y + w2 * c0.y + w3 * (r.y * scale * wn.y);
    float o2 = w0 * a0.z + w1 * a1.z + w2 * c0.z + w3 * (r.z * scale * wn.z);
    float o3 = w0 * a0.w + w1 * a1.w + w2 * c0.w + w3 * (r.w * scale * wn.w);
    __half2* op = (__half2*)(omix + r4 * 4);
    op[0] = __floats2half2_rn(o0, o1);
    op[1] = __floats2half2_rn(o2, o3);
}

// res2 (fp32, output) + 5-way mix -> fp16 (pre-transpose buffer)
__global__ __launch_bounds__(256) void rms_mix_cm_kernel(
    const float* __restrict__ res1, const float* __restrict__ outm,
    const float* __restrict__ hstm, const float* __restrict__ hscm,
    const float* __restrict__ nw, const float* __restrict__ wavg,
    float* __restrict__ res2, __half* __restrict__ omix)
{
    const int bs = blockIdx.x, b = bs >> 10, s = bs & 1023, t = threadIdx.x;
    const size_t r4 = (size_t)bs * 256 + t;
    const size_t i0 = ((size_t)(b * 2 + 0) * 1024 + s) * 256 + t;
    const size_t i1 = ((size_t)(b * 2 + 1) * 1024 + s) * 256 + t;

    float4 r  = ((const float4*)res1)[r4];
    float4 om = ((const float4*)outm)[r4];
    r.x += om.x; r.y += om.y; r.z += om.z; r.w += om.w;
    ((float4*)res2)[r4] = r;

    const float tot = block_sum256(r.x * r.x + r.y * r.y + r.z * r.z + r.w * r.w);
    const float scale = rsqrtf(tot * (1.f / (float)DM) + 1e-5f);

    float w[5];
#pragma unroll
    for (int n = 0; n < 5; n++) w[n] = wavg[n * 1024 + s];
    float mx = w[0];
#pragma unroll
    for (int n = 1; n < 5; n++) mx = fmaxf(mx, w[n]);
    float sum = 0.f;
#pragma unroll
    for (int n = 0; n < 5; n++) { w[n] = __expf(w[n] - mx); sum += w[n]; }
    const float inv = 1.f / sum;
#pragma unroll
    for (int n = 0; n < 5; n++) w[n] *= inv;

    const float4 a0 = ((const float4*)hstm)[i0];
    const float4 a1 = ((const float4*)hstm)[i1];
    const float4 c0 = ((const float4*)hscm)[i0];
    const float4 c1 = ((const float4*)hscm)[i1];
    const float4 wn = ((const float4*)nw)[t];
    float o0 = w[0]*a0.x + w[1]*a1.x + w[2]*(r.x*scale*wn.x) + w[3]*c0.x + w[4]*c1.x;
    float o1 = w[0]*a0.y + w[1]*a1.y + w[2]*(r.y*scale*wn.y) + w[3]*c0.y + w[4]*c1.y;
    float o2 = w[0]*a0.z + w[1]*a1.z + w[2]*(r.z*scale*wn.z) + w[3]*c0.z + w[4]*c1.z;
    float o3 = w[0]*a0.w + w[1]*a1.w + w[2]*(r.w*scale*wn.w) + w[3]*c0.w + w[4]*c1.w;
    __half2* op = (__half2*)(omix + r4 * 4);
    op[0] = __floats2half2_rn(o0, o1);
    op[1] = __floats2half2_rn(o2, o3);
}

// batched transpose fp16 -> fp16
__global__ __launch_bounds__(256) void transpose_hh_kernel(
    const __half* __restrict__ in, __half* __restrict__ out)
{
    __shared__ __half tile[32][33];
    const int b = blockIdx.z;
    const int r0 = blockIdx.y * 32, c0 = blockIdx.x * 32;
    const size_t base = (size_t)b * 1024 * 1024;
#pragma unroll
    for (int i = threadIdx.y; i < 32; i += 8)
        tile[i][threadIdx.x] = in[base + (size_t)(r0 + i) * 1024 + c0 + threadIdx.x];
    __syncthreads();
#pragma unroll
    for (int i = threadIdx.y; i < 32; i += 8)
        out[base + (size_t)(c0 + i) * 1024 + r0 + threadIdx.x] = tile[threadIdx.x][i];
}

// batched transpose fp32 -> fp32 (final output)
__global__ __launch_bounds__(256) void transpose_kernel(
    const float* __restrict__ in, float* __restrict__ out)
{
    __shared__ float tile[32][33];
    const int b = blockIdx.z;
    const int r0 = blockIdx.y * 32, c0 = blockIdx.x * 32;
    const size_t base = (size_t)b * 1024 * 1024;
#pragma unroll
    for (int i = threadIdx.y; i < 32; i += 8)
        tile[i][threadIdx.x] = in[base + (size_t)(r0 + i) * 1024 + c0 + threadIdx.x];
    __syncthreads();
#pragma unroll
    for (int i = threadIdx.y; i < 32; i += 8)
        out[base + (size_t)(c0 + i) * 1024 + r0 + threadIdx.x] = tile[threadIdx.x][i];
}

// ---------------------------------------------------------------------------
// host side
// ---------------------------------------------------------------------------
static const int SMEMG = 3 * (128 * 80 + 128 * 80);   // 61440 per CTA

struct Bufs {
    float *xdbl, *xpart, *res1, *outm;
    __half *xzh, *xh16, *y16, *dtb16, *dth, *mix16, *tmp16, *wh;
};

static void run_mamba(const Bufs& B, const float* const* P, const __half* wbase,
                      float* out)
{
    const float* conv_w = P[1];
    const float* conv_b = P[2];
    const float* dt_b   = P[5];
    const float* A_log  = P[6];
    const float* Dp     = P[7];

    gemm_cp<0, 1><<<dim3(2 * DI_ / 128, ROWS / 128, 1), 256, SMEMG>>>(
        B.mix16, DM, wbase + W_IN, nullptr, B.xzh, ROWS, 2 * DI_, DM, DM);

    conv_silu_kernel<<<(ROWS / 4) * (DI_ / 2) / 256, 256>>>(B.xzh, conv_w, conv_b, B.xh16);

    gemm_cp<0, 0><<<dim3(1, ROWS / 128, KSP), 256, SMEMG>>>(
        B.xh16, DI_, wbase + W_XP, nullptr, B.xpart, ROWS, XD, DI_, DI_ / KSP);
    reduce_xproj_kernel<<<(ROWS * XD) / 256, 256>>>(B.xpart, B.xdbl, B.dth);

    gemm_cp<1, 1><<<dim3(DI_ / 128, ROWS / 128, 1), 256, SMEMG>>>(
        B.dth, DTR, wbase + W_DT, dt_b, B.dtb16, ROWS, DI_, DTR, DTR);

    scan_kernel<<<dim3(DI_ / 32, BSZ), 32>>>(B.dtb16, B.xh16, B.xdbl, B.xzh,
                                             A_log, Dp, B.y16);

    gemm_cp<0, 0><<<dim3(DM / 128, ROWS / 128, 1), 256, SMEMG>>>(
        B.y16, DI_, wbase + W_OUT, nullptr, out, ROWS, DM, DI_, DI_);
}

extern "C" void kernel_launch(void* const* d_in, const int* in_sizes, int n_in,
                              void* d_out, int out_size)
{
    cudaFuncSetAttribute(gemm_cp<0, 1>, cudaFuncAttributeMaxDynamicSharedMemorySize, SMEMG);
    cudaFuncSetAttribute(gemm_cp<0, 0>, cudaFuncAttributeMaxDynamicSharedMemorySize, SMEMG);
    cudaFuncSetAttribute(gemm_cp<1, 1>, cudaFuncAttributeMaxDynamicSharedMemorySize, SMEMG);

    const float* hstm     = (const float*)d_in[0];
    const float* hscm     = (const float*)d_in[1];
    const float* residual = (const float*)d_in[2];
    const float* norm_tm  = (const float*)d_in[3];
    const float* wavg_tm  = (const float*)d_in[4];

    const float *norm_cm, *wavg_cm;
    int btm;
    const int bcm = 16;
    if (in_sizes[5] == 1024) {            // dict order
        norm_cm = (const float*)d_in[5];
        wavg_cm = (const float*)d_in[6];
        btm = 7;
    } else {                              // signature order
        btm = 5;
        norm_cm = (const float*)d_in[14];
        wavg_cm = (const float*)d_in[15];
    }
    const float* P_tm[9];
    const float* P_cm[9];
    for (int i = 0; i < 9; i++) {
        P_tm[i] = (const float*)d_in[btm + i];
        P_cm[i] = (const float*)d_in[bcm + i];
    }

    Bufs B;
    cudaGetSymbolAddress((void**)&B.xdbl,  g_xdbl);
    cudaGetSymbolAddress((void**)&B.xpart, g_xpart);
    cudaGetSymbolAddress((void**)&B.res1,  g_res1);
    cudaGetSymbolAddress((void**)&B.outm,  g_outm);
    cudaGetSymbolAddress((void**)&B.xzh,   g_xzh);
    cudaGetSymbolAddress((void**)&B.xh16,  g_xh16);
    cudaGetSymbolAddress((void**)&B.y16,   g_y16);
    cudaGetSymbolAddress((void**)&B.dtb16, g_dtb16);
    cudaGetSymbolAddress((void**)&B.dth,   g_dth);
    cudaGetSymbolAddress((void**)&B.mix16, g_mix16);
    cudaGetSymbolAddress((void**)&B.tmp16, g_tmp16);
    cudaGetSymbolAddress((void**)&B.wh,    g_wh);

    // one fused weight conversion launch (both paths)
    W8 segs;
    segs.s[0] = { P_tm[0], B.wh + W_IN,               2 * DI_ * DM };
    segs.s[1] = { P_tm[3], B.wh + W_XP,               XD * DI_ };
    segs.s[2] = { P_tm[4], B.wh + W_DT,               DI_ * DTR };
    segs.s[3] = { P_tm[8], B.wh + W_OUT,              DM * DI_ };
    segs.s[4] = { P_cm[0], B.wh + W_STRIDE + W_IN,    2 * DI_ * DM };
    segs.s[5] = { P_cm[3], B.wh + W_STRIDE + W_XP,    XD * DI_ };
    segs.s[6] = { P_cm[4], B.wh + W_STRIDE + W_DT,    DI_ * DTR };
    segs.s[7] = { P_cm[8], B.wh + W_STRIDE + W_OUT,   DM * DI_ };
    convert_all_kernel<<<2048, 256>>>(segs);

    float* dout = (float*)d_out;
    const long total = (long)BSZ * SEQ * DM;
    float* res2_out = (out_size >= 2 * total) ? (dout + total) : B.res1;

    // --- token-mixer path ---
    rms_mix_tm_kernel<<<ROWS, 256>>>(residual, hstm, hscm, norm_tm, wavg_tm,
                                     B.res1, B.mix16);
    run_mamba(B, P_tm, B.wh, B.outm);

    // --- channel-mixer path ---
    rms_mix_cm_kernel<<<ROWS, 256>>>(B.res1, B.outm, hstm, hscm, norm_cm, wavg_cm,
                                     res2_out, B.tmp16);
    transpose_hh_kernel<<<dim3(32, 32, BSZ), dim3(32, 8)>>>(B.tmp16, B.mix16);
    run_mamba(B, P_cm, B.wh + W_STRIDE, B.outm);
    transpose_kernel<<<dim3(32, 32, BSZ), dim3(32, 8)>>>(B.outm, dout);
}

// round 16
// speedup vs baseline: 1.1874x; 1.1874x over previous
#include <cuda_runtime.h>
#include <cuda_fp16.h>
#include <cstdint>
#include <math.h>

// ---------------------------------------------------------------------------
// SambaMixerBlock: B=8, S=D=1024, N=16, DCONV=4, EXPAND=2 -> DI=2048, DT_RANK=64
// Round 16: chunked two-pass scan (NC=8 chunks of 128): pass1 computes per-
//           chunk partial state S and decay product P at 8x parallelism,
//           combine runs the 8-step cross-chunk recurrence, pass2 re-scans
//           each chunk from its true initial state. Base = round-14 (QD=8).
// ---------------------------------------------------------------------------

#define BSZ   8
#define SEQ   1024
#define DM    1024
#define DI_   2048
#define NST   16
#define DTR   64
#define XD    96
#define ROWS  (BSZ*SEQ)
#define KSP   4                      // x_proj split-K factor
#define QD    8                      // scan prefetch queue depth
#define NC    8                      // scan chunks
#define CHK   (SEQ/NC)               // 128
#define DN    (DI_*NST)

// fp32 scratch
__device__ float g_xdbl[(size_t)ROWS * XD];
__device__ float g_xpart[(size_t)KSP * ROWS * XD];
__device__ float g_res1[(size_t)ROWS * DM];
__device__ float g_outm[(size_t)ROWS * DM];
__device__ float g_S [(size_t)BSZ * NC * DN];
__device__ float g_P [(size_t)BSZ * NC * DN];
__device__ float g_H0[(size_t)BSZ * NC * DN];
// fp16 scratch
__device__ __half g_xzh [(size_t)ROWS * 2 * DI_];
__device__ __half g_xh16[(size_t)ROWS * DI_];
__device__ __half g_y16 [(size_t)ROWS * DI_];
__device__ __half g_dtb16[(size_t)ROWS * DI_];
__device__ __half g_dth [(size_t)ROWS * DTR];
__device__ __half g_mix16[(size_t)ROWS * DM];
__device__ __half g_tmp16[(size_t)ROWS * DM];

// converted weights: per path IN | XPROJ | DT | OUT
#define W_IN   0
#define W_XP   (2 * DI_ * DM)
#define W_DT   (W_XP + XD * DI_)
#define W_OUT  (W_DT + DI_ * DTR)
#define W_STRIDE (W_OUT + DM * DI_)
__device__ __half g_wh[(size_t)2 * W_STRIDE];

// ---------------------------------------------------------------------------
__device__ __forceinline__ void cpa16(uint32_t d, const void* s)
{
    asm volatile("cp.async.cg.shared.global [%0], [%1], 16;" :: "r"(d), "l"(s));
}
__device__ __forceinline__ void cpa16z(uint32_t d, const void* s, bool ok)
{
    int sz = ok ? 16 : 0;
    asm volatile("cp.async.cg.shared.global [%0], [%1], 16, %2;"
                 :: "r"(d), "l"(s), "r"(sz));
}
#define CP_COMMIT() asm volatile("cp.async.commit_group;" ::: "memory")
#define CP_WAIT1()  asm volatile("cp.async.wait_group 1;" ::: "memory")

__device__ __forceinline__ void mma16816(float* d, const uint32_t* a, const uint32_t* b)
{
    asm volatile(
        "mma.sync.aligned.m16n8k16.row.col.f32.f16.f16.f32 "
        "{%0,%1,%2,%3}, {%4,%5,%6,%7}, {%8,%9}, {%0,%1,%2,%3};"
        : "+f"(d[0]), "+f"(d[1]), "+f"(d[2]), "+f"(d[3])
        : "r"(a[0]), "r"(a[1]), "r"(a[2]), "r"(a[3]), "r"(b[0]), "r"(b[1]));
}

__device__ __forceinline__ void ldmx4(uint32_t* r, uint32_t addr)
{
    asm volatile("ldmatrix.sync.aligned.m8n8.x4.shared.b16 {%0,%1,%2,%3}, [%4];"
                 : "=r"(r[0]), "=r"(r[1]), "=r"(r[2]), "=r"(r[3]) : "r"(addr));
}

// ---------------------------------------------------------------------------
// Pipelined HMMA GEMM: CTA 128x128, 8 warps (64x32), BK=32, 3-stage cp.async,
// ldmatrix, 80B row stride, 2 CTAs/SM. EPI: softplus(C+bias). OUTH: fp16 C.
// ---------------------------------------------------------------------------
template<int EPI, int OUTH>
__global__ __launch_bounds__(256, 2) void gemm_cp(
    const __half* __restrict__ A, int lda,
    const __half* __restrict__ Bm,
    const float* __restrict__ bias, void* __restrict__ Cbase,
    int M, int Nsz, int Kfull, int Ksub)
{
    constexpr int TN  = 128;
    constexpr int ABY = 128 * 80;
    constexpr int BBY = TN * 80;
    constexpr int STG = ABY + BBY;
    constexpr int JN  = TN / 32;

    extern __shared__ __align__(16) char smem[];
    const uint32_t sb0 = (uint32_t)__cvta_generic_to_shared(smem);

    const int tid = threadIdx.x, wid = tid >> 5, lid = tid & 31;
    const int bm = blockIdx.y * 128, bn = blockIdx.x * TN;
    const int koff = blockIdx.z * Ksub;
    const int wm = (wid & 1) * 64, wn = (wid >> 1) * 32;
    const int g = lid >> 2, t4 = lid & 3;
    const int S = Ksub >> 5;

    const int lr = lid & 7, tq = lid >> 3;
    const int a_ro = (tq & 1) * 8, a_co = (tq >> 1) * 16;
    const int b_ro = (tq >> 1) * 8, b_co = (tq & 1) * 16;

    auto issue = [&](int s) {
        const int k0 = koff + (s << 5);
        const uint32_t st = sb0 + (s % 3) * STG;
#pragma unroll
        for (int i = 0; i < 2; i++) {
            const int id = tid + i * 256, row = id >> 2, q = id & 3;
            const size_t go = (size_t)(bm + row) * lda + k0 + q * 8;
            cpa16(st + row * 80 + q * 16, A + go);
        }
#pragma unroll
        for (int i = 0; i < 2; i++) {
            const int id = tid + i * 256, row = id >> 2, q = id & 3;
            const bool ok = (bn + row) < Nsz;
            const int r2 = ok ? (bn + row) : 0;
            const size_t go = (size_t)r2 * Kfull + k0 + q * 8;
            cpa16z(st + ABY + row * 80 + q * 16, Bm + go, ok);
        }
    };

    float acc[4][JN][4];
#pragma unroll
    for (int i = 0; i < 4; i++)
#pragma unroll
        for (int j = 0; j < JN; j++)
#pragma unroll
            for (int c = 0; c < 4; c++) acc[i][j][c] = 0.f;

    issue(0); CP_COMMIT();
    if (S > 1) issue(1);
    CP_COMMIT();

    for (int s = 0; s < S; s++) {
        CP_WAIT1();
        __syncthreads();
        if (s + 2 < S) issue(s + 2);
        CP_COMMIT();

        const uint32_t st = sb0 + (s % 3) * STG;
#pragma unroll
        for (int kk = 0; kk < 2; kk++) {
            const int cb = kk * 32;
            uint32_t ah[4][4];
#pragma unroll
            for (int i = 0; i < 4; i++)
                ldmx4(ah[i], st + (wm + i * 16 + a_ro + lr) * 80 + cb + a_co);
#pragma unroll
            for (int j2 = 0; j2 < JN / 2; j2++) {
                uint32_t bh[4];
                ldmx4(bh, st + ABY + (wn + j2 * 16 + b_ro + lr) * 80 + cb + b_co);
#pragma unroll
                for (int i = 0; i < 4; i++) {
                    mma16816(acc[i][2 * j2],     ah[i], bh);
                    mma16816(acc[i][2 * j2 + 1], ah[i], bh + 2);
                }
            }
        }
    }

#pragma unroll
    for (int i = 0; i < 4; i++) {
        const int r0 = bm + wm + i * 16 + g;
#pragma unroll
        for (int j = 0; j < JN; j++) {
            const int c = bn + wn + j * 8 + t4 * 2;
            if (c < Nsz) {
                float v0 = acc[i][j][0], v1 = acc[i][j][1];
                float v2 = acc[i][j][2], v3 = acc[i][j][3];
                if (EPI == 1) {
                    const float b0 = bias[c], b1 = bias[c + 1];
                    v0 += b0; v1 += b1; v2 += b0; v3 += b1;
                    v0 = (v0 > 20.f) ? v0 : __logf(1.f + __expf(v0));
                    v1 = (v1 > 20.f) ? v1 : __logf(1.f + __expf(v1));
                    v2 = (v2 > 20.f) ? v2 : __logf(1.f + __expf(v2));
                    v3 = (v3 > 20.f) ? v3 : __logf(1.f + __expf(v3));
                }
                if (OUTH) {
                    __half* C = (__half*)Cbase + (size_t)blockIdx.z * M * Nsz;
                    *(__half2*)(C + (size_t)r0 * Nsz + c) = __floats2half2_rn(v0, v1);
                    *(__half2*)(C + (size_t)(r0 + 8) * Nsz + c) = __floats2half2_rn(v2, v3);
                } else {
                    float* C = (float*)Cbase + (size_t)blockIdx.z * M * Nsz;
                    *(float2*)(C + (size_t)r0 * Nsz + c)       = make_float2(v0, v1);
                    *(float2*)(C + (size_t)(r0 + 8) * Nsz + c) = make_float2(v2, v3);
                }
            }
        }
    }
}

// ---------------------------------------------------------------------------
struct WSeg { const float* src; __half* dst; int n; };
struct W8   { WSeg s[8]; };

__global__ __launch_bounds__(256) void convert_all_kernel(W8 segs)
{
    const int stride = gridDim.x * 256;
    const int t0 = blockIdx.x * 256 + threadIdx.x;
#pragma unroll
    for (int k = 0; k < 8; k++) {
        const float* src = segs.s[k].src;
        __half* dst = segs.s[k].dst;
        const int n = segs.s[k].n;
        for (int i = t0; i < n; i += stride)
            dst[i] = __float2half_rn(src[i]);
    }
}

__global__ __launch_bounds__(256) void reduce_xproj_kernel(
    const float* __restrict__ part, float* __restrict__ xdbl,
    __half* __restrict__ dth)
{
    const size_t n1 = (size_t)ROWS * XD;
    const size_t i = (size_t)blockIdx.x * 256 + threadIdx.x;
    float s = part[i] + part[i + n1] + part[i + 2 * n1] + part[i + 3 * n1];
    xdbl[i] = s;
    const int col = (int)(i % XD);
    if (col < DTR) dth[(i / XD) * DTR + col] = __float2half_rn(s);
}

// ---------------------------------------------------------------------------
// Depthwise causal conv + bias + SiLU; 2 channels x 4 l-steps per thread.
// ---------------------------------------------------------------------------
__global__ __launch_bounds__(256) void conv_silu_kernel(
    const __half* __restrict__ xz, const float* __restrict__ w,
    const float* __restrict__ bias, __half* __restrict__ xh)
{
    const long i = (long)blockIdx.x * 256 + threadIdx.x;
    const int  d2 = (int)(i & (DI_ / 2 - 1));
    const int  d  = d2 * 2;
    const long bl4 = i >> 10;
    const int  l0 = (int)(bl4 & (SEQ / 4 - 1)) * 4;
    const long b  = bl4 >> 8;

    const __half* base = xz + ((size_t)b * SEQ) * (2 * DI_) + d;
    const float2 bs = *(const float2*)(bias + d);
    const float4 wa = *(const float4*)(w + d * 4);
    const float4 wb = *(const float4*)(w + d * 4 + 4);

    float2 f[7];
#pragma unroll
    for (int j = 0; j < 7; j++) {
        const int l = l0 - 3 + j;
        if (l >= 0)
            f[j] = __half22float2(*(const __half2*)(base + (size_t)l * (2 * DI_)));
        else
            f[j] = make_float2(0.f, 0.f);
    }

    __half* op = xh + ((size_t)b * SEQ + l0) * DI_ + d;
#pragma unroll
    for (int k = 0; k < 4; k++) {
        float a0 = bs.x + wa.x * f[k].x + wa.y * f[k + 1].x
                        + wa.z * f[k + 2].x + wa.w * f[k + 3].x;
        float a1 = bs.y + wb.x * f[k].y + wb.y * f[k + 1].y
                        + wb.z * f[k + 2].y + wb.w * f[k + 3].y;
        a0 = a0 / (1.f + __expf(-a0));
        a1 = a1 / (1.f + __expf(-a1));
        *(__half2*)(op + (size_t)k * DI_) = __floats2half2_rn(a0, a1);
    }
}

// ---------------------------------------------------------------------------
// Chunked scan, pass 1: per-chunk partial state S (from h=0) and decay
// product P. grid = (DI/32, BSZ, NC), 1 warp/block.
// ---------------------------------------------------------------------------
__global__ __launch_bounds__(32) void scan_pass1(
    const __half* __restrict__ dtb, const __half* __restrict__ xh,
    const float* __restrict__ xdbl, const float* __restrict__ A_log,
    float* __restrict__ Sout, float* __restrict__ Pout)
{
    const int b = blockIdx.y, c = blockIdx.z;
    const int lane = threadIdx.x;
    const int d = blockIdx.x * 32 + lane;

    float A[NST], h[NST], Pr[NST];
#pragma unroll
    for (int n = 0; n < NST; n++) {
        A[n] = -__expf(A_log[d * NST + n]);
        h[n] = 0.f;
        Pr[n] = 1.f;
    }
    const float A0 = A[0];
    bool uni = true;
#pragma unroll
    for (int n = 1; n < NST; n++)
        uni = uni && (fabsf(A[n] - (n + 1) * A0) <= 1e-3f * (n + 1) * fabsf(A0) + 1e-12f);

    const size_t rowbase = (size_t)b * SEQ + (size_t)c * CHK;

    __half dq[QD], xq[QD];
    float bcq[QD];
#pragma unroll
    for (int p = 0; p < QD; p++) {
        const size_t idx = (rowbase + p) * DI_ + d;
        dq[p]  = dtb[idx];
        xq[p]  = xh[idx];
        bcq[p] = xdbl[(rowbase + p) * XD + DTR + lane];
    }

    for (int l0 = 0; l0 < CHK; l0 += QD) {
#pragma unroll
        for (int p = 0; p < QD; p++) {
            const int l = l0 + p;
            const float dtv = __half2float(dq[p]);
            const float xv  = __half2float(xq[p]);
            const float bcv = bcq[p];

            const int lp = (l + QD < CHK) ? l + QD : CHK - 1;
            const size_t idx2 = (rowbase + lp) * DI_ + d;
            dq[p]  = dtb[idx2];
            xq[p]  = xh[idx2];
            bcq[p] = xdbl[(rowbase + lp) * XD + DTR + lane];

            const float dx = dtv * xv;
            if (uni) {
                const float p1 = __expf(dtv * A0);
                float e[NST];
                e[0] = p1;
                e[1] = p1 * p1;
                e[2] = e[1] * p1;
                e[3] = e[1] * e[1];
#pragma unroll
                for (int n = 4; n < NST; n++) e[n] = e[n - 4] * e[3];
#pragma unroll
                for (int n = 0; n < NST; n++) {
                    const float Bn = __shfl_sync(0xffffffffu, bcv, n);
                    h[n]  = e[n] * h[n] + dx * Bn;
                    Pr[n] *= e[n];
                }
            } else {
#pragma unroll
                for (int n = 0; n < NST; n++) {
                    const float Bn = __shfl_sync(0xffffffffu, bcv, n);
                    const float en = __expf(dtv * A[n]);
                    h[n]  = en * h[n] + dx * Bn;
                    Pr[n] *= en;
                }
            }
        }
    }

    const size_t o = (((size_t)b * NC + c) * DI_ + d) * NST;
#pragma unroll
    for (int n = 0; n < NST; n++) {
        Sout[o + n] = h[n];
        Pout[o + n] = Pr[n];
    }
}

// cross-chunk combine: h0[c] = S[c-1] + P[c-1]*h0[c-1], h0[0]=0.
__global__ __launch_bounds__(256) void scan_combine(
    const float* __restrict__ S, const float* __restrict__ P,
    float* __restrict__ H0)
{
    const size_t t = (size_t)blockIdx.x * 256 + threadIdx.x;   // over BSZ*DN
    const size_t b = t / DN;
    const size_t r = t - b * DN;
    float h = 0.f;
#pragma unroll
    for (int c = 0; c < NC; c++) {
        const size_t o = (b * NC + c) * DN + r;
        H0[o] = h;
        h = S[o] + P[o] * h;
    }
}

// ---------------------------------------------------------------------------
// Chunked scan, pass 2: scan each chunk from its true h0, emit y.
// grid = (DI/32, BSZ, NC), 1 warp/block.
// ---------------------------------------------------------------------------
__global__ __launch_bounds__(32) void scan_pass2(
    const __half* __restrict__ dtb, const __half* __restrict__ xh,
    const float* __restrict__ xdbl, const __half* __restrict__ xz,
    const float* __restrict__ A_log, const float* __restrict__ Dp,
    const float* __restrict__ H0, __half* __restrict__ y)
{
    const int b = blockIdx.y, c = blockIdx.z;
    const int lane = threadIdx.x;
    const int d = blockIdx.x * 32 + lane;

    float A[NST], h[NST];
    const size_t o = (((size_t)b * NC + c) * DI_ + d) * NST;
#pragma unroll
    for (int n = 0; n < NST; n++) {
        A[n] = -__expf(A_log[d * NST + n]);
        h[n] = H0[o + n];
    }
    const float A0 = A[0];
    bool uni = true;
#pragma unroll
    for (int n = 1; n < NST; n++)
        uni = uni && (fabsf(A[n] - (n + 1) * A0) <= 1e-3f * (n + 1) * fabsf(A0) + 1e-12f);
    const float dval = Dp[d];

    const size_t rowbase = (size_t)b * SEQ + (size_t)c * CHK;

    __half dq[QD], xq[QD], zq[QD];
    float bcq[QD];
#pragma unroll
    for (int p = 0; p < QD; p++) {
        const size_t idx = (rowbase + p) * DI_ + d;
        dq[p]  = dtb[idx];
        xq[p]  = xh[idx];
        zq[p]  = xz[(rowbase + p) * (2 * DI_) + DI_ + d];
        bcq[p] = xdbl[(rowbase + p) * XD + DTR + lane];
    }

    for (int l0 = 0; l0 < CHK; l0 += QD) {
#pragma unroll
        for (int p = 0; p < QD; p++) {
            const int l = l0 + p;
            const float dtv = __half2float(dq[p]);
            const float xv  = __half2float(xq[p]);
            const float zv  = __half2float(zq[p]);
            const float bcv = bcq[p];

            const int lp = (l + QD < CHK) ? l + QD : CHK - 1;
            const size_t idx2 = (rowbase + lp) * DI_ + d;
            dq[p]  = dtb[idx2];
            xq[p]  = xh[idx2];
            zq[p]  = xz[(rowbase + lp) * (2 * DI_) + DI_ + d];
            bcq[p] = xdbl[(rowbase + lp) * XD + DTR + lane];

            const float dx = dtv * xv;
            float acc4[4] = {0.f, 0.f, 0.f, 0.f};
            if (uni) {
                const float p1 = __expf(dtv * A0);
                float e[NST];
                e[0] = p1;
                e[1] = p1 * p1;
                e[2] = e[1] * p1;
                e[3] = e[1] * e[1];
#pragma unroll
                for (int n = 4; n < NST; n++) e[n] = e[n - 4] * e[3];
#pragma unroll
                for (int n = 0; n < NST; n++) {
                    const float Bn = __shfl_sync(0xffffffffu, bcv, n);
                    const float Cn = __shfl_sync(0xffffffffu, bcv, 16 + n);
                    h[n] = e[n] * h[n] + dx * Bn;
                    acc4[n & 3] += h[n] * Cn;
                }
            } else {
#pragma unroll
                for (int n = 0; n < NST; n++) {
                    const float Bn = __shfl_sync(0xffffffffu, bcv, n);
                    const float Cn = __shfl_sync(0xffffffffu, bcv, 16 + n);
                    h[n] = __expf(dtv * A[n]) * h[n] + dx * Bn;
                    acc4[n & 3] += h[n] * Cn;
                }
            }
            float acc = (acc4[0] + acc4[1]) + (acc4[2] + acc4[3]);
            acc += xv * dval;
            acc *= zv / (1.f + __expf(-zv));
            y[(rowbase + l) * DI_ + d] = __float2half_rn(acc);
        }
    }
}

// ---------------------------------------------------------------------------
__device__ __forceinline__ float block_sum256(float v)
{
    __shared__ float red[8];
    const int lane = threadIdx.x & 31, w = threadIdx.x >> 5;
#pragma unroll
    for (int o = 16; o; o >>= 1) v += __shfl_xor_sync(0xffffffffu, v, o);
    if (!lane) red[w] = v;
    __syncthreads();
    if (w == 0) {
        v = (lane < 8) ? red[lane] : 0.f;
#pragma unroll
        for (int o = 4; o; o >>= 1) v += __shfl_xor_sync(0xffffffffu, v, o);
        if (!lane) red[0] = v;
    }
    __syncthreads();
    return red[0];
}

__global__ __launch_bounds__(256) void rms_mix_tm_kernel(
    const float* __restrict__ residual, const float* __restrict__ hstm,
    const float* __restrict__ hscm, const float* __restrict__ nw,
    const float* __restrict__ wavg, float* __restrict__ res1,
    __half* __restrict__ omix)
{
    const int bs = blockIdx.x, b = bs >> 10, s = bs & 1023, t = threadIdx.x;
    const size_t r4 = (size_t)bs * 256 + t;
    const size_t i0 = ((size_t)(b * 2 + 0) * 1024 + s) * 256 + t;
    const size_t i1 = ((size_t)(b * 2 + 1) * 1024 + s) * 256 + t;

    float4 r  = ((const float4*)residual)[r4];
    float4 c1 = ((const float4*)hscm)[i1];
    r.x += c1.x; r.y += c1.y; r.z += c1.z; r.w += c1.w;
    ((float4*)res1)[r4] = r;

    const float tot = block_sum256(r.x * r.x + r.y * r.y + r.z * r.z + r.w * r.w);
    const float scale = rsqrtf(tot * (1.f / (float)DM) + 1e-5f);

    float w0 = wavg[s], w1 = wavg[1024 + s], w2 = wavg[2048 + s], w3 = wavg[3072 + s];
    const float mx = fmaxf(fmaxf(w0, w1), fmaxf(w2, w3));
    w0 = __expf(w0 - mx); w1 = __expf(w1 - mx); w2 = __expf(w2 - mx); w3 = __expf(w3 - mx);
    const float inv = 1.f / (w0 + w1 + w2 + w3);
    w0 *= inv; w1 *= inv; w2 *= inv; w3 *= inv;

    const float4 a0 = ((const float4*)hstm)[i0];
    const float4 a1 = ((const float4*)hstm)[i1];
    const float4 c0 = ((const float4*)hscm)[i0];
    const float4 wn = ((const float4*)nw)[t];
    float o0 = w0 * a0.x + w1 * a1.x + w2 * c0.x + w3 * (r.x * scale * wn.x);
    float o1 = w0 * a0.y + w1 * a1.y + w2 * c0.y + w3 * (r.y * scale * wn.y);
    float o2 = w0 * a0.z + w1 * a1.z + w2 * c0.z + w3 * (r.z * scale * wn.z);
    float o3 = w0 * a0.w + w1 * a1.w + w2 * c0.w + w3 * (r.w * scale * wn.w);
    __half2* op = (__half2*)(omix + r4 * 4);
    op[0] = __floats2half2_rn(o0, o1);
    op[1] = __floats2half2_rn(o2, o3);
}

// res2 (fp32, output) + 5-way mix -> fp16 (pre-transpose buffer)
__global__ __launch_bounds__(256) void rms_mix_cm_kernel(
    const float* __restrict__ res1, const float* __restrict__ outm,
    const float* __restrict__ hstm, const float* __restrict__ hscm,
    const float* __restrict__ nw, const float* __restrict__ wavg,
    float* __restrict__ res2, __half* __restrict__ omix)
{
    const int bs = blockIdx.x, b = bs >> 10, s = bs & 1023, t = threadIdx.x;
    const size_t r4 = (size_t)bs * 256 + t;
    const size_t i0 = ((size_t)(b * 2 + 0) * 1024 + s) * 256 + t;
    const size_t i1 = ((size_t)(b * 2 + 1) * 1024 + s) * 256 + t;

    float4 r  = ((const float4*)res1)[r4];
    float4 om = ((const float4*)outm)[r4];
    r.x += om.x; r.y += om.y; r.z += om.z; r.w += om.w;
    ((float4*)res2)[r4] = r;

    const float tot = block_sum256(r.x * r.x + r.y * r.y + r.z * r.z + r.w * r.w);
    const float scale = rsqrtf(tot * (1.f / (float)DM) + 1e-5f);

    float w[5];
#pragma unroll
    for (int n = 0; n < 5; n++) w[n] = wavg[n * 1024 + s];
    float mx = w[0];
#pragma unroll
    for (int n = 1; n < 5; n++) mx = fmaxf(mx, w[n]);
    float sum = 0.f;
#pragma unroll
    for (int n = 0; n < 5; n++) { w[n] = __expf(w[n] - mx); sum += w[n]; }
    const float inv = 1.f / sum;
#pragma unroll
    for (int n = 0; n < 5; n++) w[n] *= inv;

    const float4 a0 = ((const float4*)hstm)[i0];
    const float4 a1 = ((const float4*)hstm)[i1];
    const float4 c0 = ((const float4*)hscm)[i0];
    const float4 c1 = ((const float4*)hscm)[i1];
    const float4 wn = ((const float4*)nw)[t];
    float o0 = w[0]*a0.x + w[1]*a1.x + w[2]*(r.x*scale*wn.x) + w[3]*c0.x + w[4]*c1.x;
    float o1 = w[0]*a0.y + w[1]*a1.y + w[2]*(r.y*scale*wn.y) + w[3]*c0.y + w[4]*c1.y;
    float o2 = w[0]*a0.z + w[1]*a1.z + w[2]*(r.z*scale*wn.z) + w[3]*c0.z + w[4]*c1.z;
    float o3 = w[0]*a0.w + w[1]*a1.w + w[2]*(r.w*scale*wn.w) + w[3]*c0.w + w[4]*c1.w;
    __half2* op = (__half2*)(omix + r4 * 4);
    op[0] = __floats2half2_rn(o0, o1);
    op[1] = __floats2half2_rn(o2, o3);
}

// batched transpose fp16 -> fp16
__global__ __launch_bounds__(256) void transpose_hh_kernel(
    const __half* __restrict__ in, __half* __restrict__ out)
{
    __shared__ __half tile[32][33];
    const int b = blockIdx.z;
    const int r0 = blockIdx.y * 32, c0 = blockIdx.x * 32;
    const size_t base = (size_t)b * 1024 * 1024;
#pragma unroll
    for (int i = threadIdx.y; i < 32; i += 8)
        tile[i][threadIdx.x] = in[base + (size_t)(r0 + i) * 1024 + c0 + threadIdx.x];
    __syncthreads();
#pragma unroll
    for (int i = threadIdx.y; i < 32; i += 8)
        out[base + (size_t)(c0 + i) * 1024 + r0 + threadIdx.x] = tile[threadIdx.x][i];
}

// batched transpose fp32 -> fp32 (final output)
__global__ __launch_bounds__(256) void transpose_kernel(
    const float* __restrict__ in, float* __restrict__ out)
{
    __shared__ float tile[32][33];
    const int b = blockIdx.z;
    const int r0 = blockIdx.y * 32, c0 = blockIdx.x * 32;
    const size_t base = (size_t)b * 1024 * 1024;
#pragma unroll
    for (int i = threadIdx.y; i < 32; i += 8)
        tile[i][threadIdx.x] = in[base + (size_t)(r0 + i) * 1024 + c0 + threadIdx.x];
    __syncthreads();
#pragma unroll
    for (int i = threadIdx.y; i < 32; i += 8)
        out[base + (size_t)(c0 + i) * 1024 + r0 + threadIdx.x] = tile[threadIdx.x][i];
}

// ---------------------------------------------------------------------------
// host side
// ---------------------------------------------------------------------------
static const int SMEMG = 3 * (128 * 80 + 128 * 80);   // 61440 per CTA

struct Bufs {
    float *xdbl, *xpart, *res1, *outm, *S, *P, *H0;
    __half *xzh, *xh16, *y16, *dtb16, *dth, *mix16, *tmp16, *wh;
};

static void run_mamba(const Bufs& B, const float* const* P, const __half* wbase,
                      float* out)
{
    const float* conv_w = P[1];
    const float* conv_b = P[2];
    const float* dt_b   = P[5];
    const float* A_log  = P[6];
    const float* Dp     = P[7];

    gemm_cp<0, 1><<<dim3(2 * DI_ / 128, ROWS / 128, 1), 256, SMEMG>>>(
        B.mix16, DM, wbase + W_IN, nullptr, B.xzh, ROWS, 2 * DI_, DM, DM);

    conv_silu_kernel<<<(ROWS / 4) * (DI_ / 2) / 256, 256>>>(B.xzh, conv_w, conv_b, B.xh16);

    gemm_cp<0, 0><<<dim3(1, ROWS / 128, KSP), 256, SMEMG>>>(
        B.xh16, DI_, wbase + W_XP, nullptr, B.xpart, ROWS, XD, DI_, DI_ / KSP);
    reduce_xproj_kernel<<<(ROWS * XD) / 256, 256>>>(B.xpart, B.xdbl, B.dth);

    gemm_cp<1, 1><<<dim3(DI_ / 128, ROWS / 128, 1), 256, SMEMG>>>(
        B.dth, DTR, wbase + W_DT, dt_b, B.dtb16, ROWS, DI_, DTR, DTR);

    // chunked two-pass scan
    scan_pass1<<<dim3(DI_ / 32, BSZ, NC), 32>>>(B.dtb16, B.xh16, B.xdbl,
                                                A_log, B.S, B.P);
    scan_combine<<<(BSZ * DN) / 256, 256>>>(B.S, B.P, B.H0);
    scan_pass2<<<dim3(DI_ / 32, BSZ, NC), 32>>>(B.dtb16, B.xh16, B.xdbl, B.xzh,
                                                A_log, Dp, B.H0, B.y16);

    gemm_cp<0, 0><<<dim3(DM / 128, ROWS / 128, 1), 256, SMEMG>>>(
        B.y16, DI_, wbase + W_OUT, nullptr, out, ROWS, DM, DI_, DI_);
}

extern "C" void kernel_launch(void* const* d_in, const int* in_sizes, int n_in,
                              void* d_out, int out_size)
{
    cudaFuncSetAttribute(gemm_cp<0, 1>, cudaFuncAttributeMaxDynamicSharedMemorySize, SMEMG);
    cudaFuncSetAttribute(gemm_cp<0, 0>, cudaFuncAttributeMaxDynamicSharedMemorySize, SMEMG);
    cudaFuncSetAttribute(gemm_cp<1, 1>, cudaFuncAttributeMaxDynamicSharedMemorySize, SMEMG);

    const float* hstm     = (const float*)d_in[0];
    const float* hscm     = (const float*)d_in[1];
    const float* residual = (const float*)d_in[2];
    const float* norm_tm  = (const float*)d_in[3];
    const float* wavg_tm  = (const float*)d_in[4];

    const float *norm_cm, *wavg_cm;
    int btm;
    const int bcm = 16;
    if (in_sizes[5] == 1024) {            // dict order
        norm_cm = (const float*)d_in[5];
        wavg_cm = (const float*)d_in[6];
        btm = 7;
    } else {                              // signature order
        btm = 5;
        norm_cm = (const float*)d_in[14];
        wavg_cm = (const float*)d_in[15];
    }
    const float* P_tm[9];
    const float* P_cm[9];
    for (int i = 0; i < 9; i++) {
        P_tm[i] = (const float*)d_in[btm + i];
        P_cm[i] = (const float*)d_in[bcm + i];
    }

    Bufs B;
    cudaGetSymbolAddress((void**)&B.xdbl,  g_xdbl);
    cudaGetSymbolAddress((void**)&B.xpart, g_xpart);
    cudaGetSymbolAddress((void**)&B.res1,  g_res1);
    cudaGetSymbolAddress((void**)&B.outm,  g_outm);
    cudaGetSymbolAddress((void**)&B.S,     g_S);
    cudaGetSymbolAddress((void**)&B.P,     g_P);
    cudaGetSymbolAddress((void**)&B.H0,    g_H0);
    cudaGetSymbolAddress((void**)&B.xzh,   g_xzh);
    cudaGetSymbolAddress((void**)&B.xh16,  g_xh16);
    cudaGetSymbolAddress((void**)&B.y16,   g_y16);
    cudaGetSymbolAddress((void**)&B.dtb16, g_dtb16);
    cudaGetSymbolAddress((void**)&B.dth,   g_dth);
    cudaGetSymbolAddress((void**)&B.mix16, g_mix16);
    cudaGetSymbolAddress((void**)&B.tmp16, g_tmp16);
    cudaGetSymbolAddress((void**)&B.wh,    g_wh);

    // one fused weight conversion launch (both paths)
    W8 segs;
    segs.s[0] = { P_tm[0], B.wh + W_IN,               2 * DI_ * DM };
    segs.s[1] = { P_tm[3], B.wh + W_XP,               XD * DI_ };
    segs.s[2] = { P_tm[4], B.wh + W_DT,               DI_ * DTR };
    segs.s[3] = { P_tm[8], B.wh + W_OUT,              DM * DI_ };
    segs.s[4] = { P_cm[0], B.wh + W_STRIDE + W_IN,    2 * DI_ * DM };
    segs.s[5] = { P_cm[3], B.wh + W_STRIDE + W_XP,    XD * DI_ };
    segs.s[6] = { P_cm[4], B.wh + W_STRIDE + W_DT,    DI_ * DTR };
    segs.s[7] = { P_cm[8], B.wh + W_STRIDE + W_OUT,   DM * DI_ };
    convert_all_kernel<<<2048, 256>>>(segs);

    float* dout = (float*)d_out;
    const long total = (long)BSZ * SEQ * DM;
    float* res2_out = (out_size >= 2 * total) ? (dout + total) : B.res1;

    // --- token-mixer path ---
    rms_mix_tm_kernel<<<ROWS, 256>>>(residual, hstm, hscm, norm_tm, wavg_tm,
                                     B.res1, B.mix16);
    run_mamba(B, P_tm, B.wh, B.outm);

    // --- channel-mixer path ---
    rms_mix_cm_kernel<<<ROWS, 256>>>(B.res1, B.outm, hstm, hscm, norm_cm, wavg_cm,
                                     res2_out, B.tmp16);
    transpose_hh_kernel<<<dim3(32, 32, BSZ), dim3(32, 8)>>>(B.tmp16, B.mix16);
    run_mamba(B, P_cm, B.wh + W_STRIDE, B.outm);
    transpose_kernel<<<dim3(32, 32, BSZ), dim3(32, 8)>>>(B.outm, dout);
}